// round 3
// baseline (speedup 1.0000x reference)
#include <cuda_runtime.h>
#include <cuda_bf16.h>

#define NN    10000
#define EE    320000
#define ET    330000    // EE + NN self loops
#define GG    100
#define CHN   250       // HEADS*OUT
#define HOUT  125
#define SLOPE 0.2f

// ---------------- scratch (static device globals; no allocation) -------------
__device__ float g_h[NN * CHN];      // pre-aggregation features h = feat @ W
__device__ float g_fa[NN * CHN];     // ping
__device__ float g_fb[NN * CHN];     // pong
__device__ float g_esrc[NN * 2];
__device__ float g_edst[NN * 2];
__device__ int   g_cnt[NN];
__device__ int   g_off[NN + 1];
__device__ int   g_pos[NN];
__device__ int   g_csr[ET];
__device__ float g_pool[GG * CHN];
__device__ float g_l1[GG * 200];
__device__ float g_l2[GG * 100];
__device__ float g_l3[GG * 100];

// ---------------- CSR build --------------------------------------------------
__global__ void zero_cnt_kernel() {
    int i = blockIdx.x * blockDim.x + threadIdx.x;
    if (i < NN) g_cnt[i] = 0;
}

__global__ void count_kernel(const int* __restrict__ ei) {
    int i = blockIdx.x * blockDim.x + threadIdx.x;
    if (i >= ET) return;
    int dst = (i < EE) ? ei[EE + i] : (i - EE);
    atomicAdd(&g_cnt[dst], 1);
}

// exclusive scan of g_cnt[0..NN) into g_off[0..NN], single block of 1024.
__global__ void scan_kernel() {
    __shared__ int sp[1024];
    int t = threadIdx.x;
    int base = t * 10;
    int loc[10];
    int sum = 0;
#pragma unroll
    for (int i = 0; i < 10; i++) {
        int idx = base + i;
        int v = (idx < NN) ? g_cnt[idx] : 0;
        loc[i] = sum;
        sum += v;
    }
    sp[t] = sum;
    __syncthreads();
    for (int off = 1; off < 1024; off <<= 1) {
        int v = (t >= off) ? sp[t - off] : 0;
        __syncthreads();
        sp[t] += v;
        __syncthreads();
    }
    int pre = sp[t] - sum;   // exclusive prefix of this thread's chunk
#pragma unroll
    for (int i = 0; i < 10; i++) {
        int idx = base + i;
        if (idx < NN) g_off[idx] = pre + loc[i];
    }
    if (t == 1023) g_off[NN] = sp[1023];
}

__global__ void init_pos_kernel() {
    int i = blockIdx.x * blockDim.x + threadIdx.x;
    if (i < NN) g_pos[i] = g_off[i];
}

__global__ void scatter_kernel(const int* __restrict__ ei) {
    int i = blockIdx.x * blockDim.x + threadIdx.x;
    if (i >= ET) return;
    int src, dst;
    if (i < EE) { src = ei[i]; dst = ei[EE + i]; }
    else        { src = i - EE; dst = i - EE; }
    int p = atomicAdd(&g_pos[dst], 1);
    g_csr[p] = src;
}

// ---------------- GEMM: C[M,Nc] = A[M,K] @ B[K,Nc]  (fp32, SIMT) -------------
#define BM 64
#define BN 64
#define BK 16
__global__ __launch_bounds__(256) void gemm_kernel(
    const float* __restrict__ A, const float* __restrict__ B,
    float* __restrict__ C, int M, int K, int Nc)
{
    __shared__ float As[BK][BM + 1];   // stored transposed
    __shared__ float Bs[BK][BN];
    int tid = threadIdx.x;
    int bm = blockIdx.y * BM;
    int bn = blockIdx.x * BN;
    int tx = tid & 15, ty = tid >> 4;

    int arow = tid >> 2;          // 0..63
    int acol = (tid & 3) * 4;     // 0,4,8,12
    int brow = tid >> 4;          // 0..15
    int bcol = (tid & 15) * 4;    // 0..60

    float acc[4][4];
#pragma unroll
    for (int i = 0; i < 4; i++)
#pragma unroll
        for (int j = 0; j < 4; j++) acc[i][j] = 0.f;

    int garow = bm + arow;
    for (int k0 = 0; k0 < K; k0 += BK) {
#pragma unroll
        for (int u = 0; u < 4; u++) {
            int gk = k0 + acol + u;
            float v = (garow < M && gk < K) ? A[(size_t)garow * K + gk] : 0.f;
            As[acol + u][arow] = v;
        }
#pragma unroll
        for (int u = 0; u < 4; u++) {
            int gk = k0 + brow;
            int gc = bn + bcol + u;
            float v = (gk < K && gc < Nc) ? B[(size_t)gk * Nc + gc] : 0.f;
            Bs[brow][bcol + u] = v;
        }
        __syncthreads();
#pragma unroll
        for (int kk = 0; kk < BK; kk++) {
            float ra[4], rb[4];
#pragma unroll
            for (int i = 0; i < 4; i++) ra[i] = As[kk][ty * 4 + i];
#pragma unroll
            for (int j = 0; j < 4; j++) rb[j] = Bs[kk][tx * 4 + j];
#pragma unroll
            for (int i = 0; i < 4; i++)
#pragma unroll
                for (int j = 0; j < 4; j++) acc[i][j] += ra[i] * rb[j];
        }
        __syncthreads();
    }
#pragma unroll
    for (int i = 0; i < 4; i++) {
        int row = bm + ty * 4 + i;
        if (row >= M) continue;
#pragma unroll
        for (int j = 0; j < 4; j++) {
            int col = bn + tx * 4 + j;
            if (col < Nc) C[(size_t)row * Nc + col] = acc[i][j];
        }
    }
}

// ---------------- attention dot products per node ----------------------------
// e_src[n,h] = sum_c h[n, h*125+c] * asrc[h*125+c]; same for adst.
__global__ void att_kernel(const float* __restrict__ asrc,
                           const float* __restrict__ adst)
{
    int warp = threadIdx.x >> 5;
    int lane = threadIdx.x & 31;
    int n = blockIdx.x * 4 + warp;
    if (n >= NN) return;
    float s0s = 0.f, s1s = 0.f, s0d = 0.f, s1d = 0.f;
    const float* hr = g_h + (size_t)n * CHN;
    for (int c = lane; c < CHN; c += 32) {
        float v = hr[c];
        float as = asrc[c], ad = adst[c];
        if (c < HOUT) { s0s += v * as; s0d += v * ad; }
        else          { s1s += v * as; s1d += v * ad; }
    }
#pragma unroll
    for (int o = 16; o; o >>= 1) {
        s0s += __shfl_xor_sync(0xffffffffu, s0s, o);
        s1s += __shfl_xor_sync(0xffffffffu, s1s, o);
        s0d += __shfl_xor_sync(0xffffffffu, s0d, o);
        s1d += __shfl_xor_sync(0xffffffffu, s1d, o);
    }
    if (lane == 0) {
        g_esrc[2 * n + 0] = s0s;
        g_esrc[2 * n + 1] = s1s;
        g_edst[2 * n + 0] = s0d;
        g_edst[2 * n + 1] = s1d;
    }
}

__device__ __forceinline__ float leaky(float x) {
    return x > 0.f ? x : SLOPE * x;
}

// ---------------- aggregation: one block per destination node ----------------
__global__ __launch_bounds__(128) void agg_kernel(const float* __restrict__ bias,
                                                  float* __restrict__ out)
{
    int i = blockIdx.x;
    int tid = threadIdx.x;
    int lane = tid & 31, warp = tid >> 5;

    __shared__ float w0[4], w1[4];
    __shared__ int   s_src[128];
    __shared__ float s_a0[128], s_a1[128];

    int s = g_off[i], e = g_off[i + 1];
    float ed0 = g_edst[2 * i], ed1 = g_edst[2 * i + 1];

    // pass 1: per-head max
    float m0 = -1e30f, m1 = -1e30f;
    for (int j = s + tid; j < e; j += 128) {
        int src = g_csr[j];
        float a0 = leaky(g_esrc[2 * src] + ed0);
        float a1 = leaky(g_esrc[2 * src + 1] + ed1);
        m0 = fmaxf(m0, a0); m1 = fmaxf(m1, a1);
    }
#pragma unroll
    for (int o = 16; o; o >>= 1) {
        m0 = fmaxf(m0, __shfl_xor_sync(0xffffffffu, m0, o));
        m1 = fmaxf(m1, __shfl_xor_sync(0xffffffffu, m1, o));
    }
    if (lane == 0) { w0[warp] = m0; w1[warp] = m1; }
    __syncthreads();
    m0 = fmaxf(fmaxf(w0[0], w0[1]), fmaxf(w0[2], w0[3]));
    m1 = fmaxf(fmaxf(w1[0], w1[1]), fmaxf(w1[2], w1[3]));
    __syncthreads();

    // pass 2: per-head denom
    float d0 = 0.f, d1 = 0.f;
    for (int j = s + tid; j < e; j += 128) {
        int src = g_csr[j];
        float a0 = leaky(g_esrc[2 * src] + ed0);
        float a1 = leaky(g_esrc[2 * src + 1] + ed1);
        d0 += __expf(a0 - m0);
        d1 += __expf(a1 - m1);
    }
#pragma unroll
    for (int o = 16; o; o >>= 1) {
        d0 += __shfl_xor_sync(0xffffffffu, d0, o);
        d1 += __shfl_xor_sync(0xffffffffu, d1, o);
    }
    if (lane == 0) { w0[warp] = d0; w1[warp] = d1; }
    __syncthreads();
    d0 = w0[0] + w0[1] + w0[2] + w0[3] + 1e-16f;
    d1 = w1[0] + w1[1] + w1[2] + w1[3] + 1e-16f;
    float r0 = 1.0f / d0, r1 = 1.0f / d1;

    // pass 3: weighted gather. thread tid handles channels 2*tid, 2*tid+1.
    float acc0 = 0.f, acc1 = 0.f;
    int c0 = 2 * tid;
    bool act = (tid < HOUT);
    bool head0a = (c0 < HOUT);       // head of channel c0
    bool head0b = (c0 + 1 < HOUT);   // head of channel c0+1

    for (int base = s; base < e; base += 128) {
        int j = base + tid;
        if (j < e) {
            int src = g_csr[j];
            float a0 = leaky(g_esrc[2 * src] + ed0);
            float a1 = leaky(g_esrc[2 * src + 1] + ed1);
            s_src[tid] = src;
            s_a0[tid] = __expf(a0 - m0) * r0;
            s_a1[tid] = __expf(a1 - m1) * r1;
        }
        __syncthreads();
        int cnt = min(128, e - base);
        if (act) {
#pragma unroll 4
            for (int k = 0; k < cnt; k++) {
                int src = s_src[k];
                float2 hv = *(const float2*)(g_h + (size_t)src * CHN + c0);
                float aa = head0a ? s_a0[k] : s_a1[k];
                float ab = head0b ? s_a0[k] : s_a1[k];
                acc0 += aa * hv.x;
                acc1 += ab * hv.y;
            }
        }
        __syncthreads();
    }
    if (act) {
        float v0 = acc0 + bias[c0];
        float v1 = acc1 + bias[c0 + 1];
        out[(size_t)i * CHN + c0]     = v0 > 0.f ? v0 : 0.f;
        out[(size_t)i * CHN + c0 + 1] = v1 > 0.f ? v1 : 0.f;
    }
}

// ---------------- global mean pool (batch sorted) -----------------------------
__global__ void pool_kernel(const int* __restrict__ batch,
                            const float* __restrict__ feat)
{
    int g = blockIdx.x;
    __shared__ int ss, se;
    if (threadIdx.x == 0) {
        int lo = 0, hi = NN;
        while (lo < hi) { int mid = (lo + hi) >> 1; if (batch[mid] < g) lo = mid + 1; else hi = mid; }
        ss = lo;
        lo = 0; hi = NN;
        while (lo < hi) { int mid = (lo + hi) >> 1; if (batch[mid] < g + 1) lo = mid + 1; else hi = mid; }
        se = lo;
    }
    __syncthreads();
    int c = threadIdx.x;
    if (c < CHN) {
        float sum = 0.f;
        for (int i = ss; i < se; i++) sum += feat[(size_t)i * CHN + c];
        float cntf = (float)(se - ss);
        g_pool[g * CHN + c] = sum / fmaxf(cntf, 1.0f);
    }
}

// ---------------- tiny linear layers -----------------------------------------
__global__ void lin_kernel(const float* __restrict__ in, const float* __restrict__ w,
                           const float* __restrict__ b, float* __restrict__ out,
                           int Gr, int K, int Dout, int relu)
{
    int idx = blockIdx.x * blockDim.x + threadIdx.x;
    if (idx >= Gr * Dout) return;
    int g = idx / Dout, j = idx % Dout;
    float s = b[j];
    for (int k = 0; k < K; k++) s += in[g * K + k] * w[k * Dout + j];
    if (relu) s = fmaxf(s, 0.f);
    out[idx] = s;
}

// ---------------- driver ------------------------------------------------------
extern "C" void kernel_launch(void* const* d_in, const int* in_sizes, int n_in,
                              void* d_out, int out_size)
{
    const float* x     = (const float*)d_in[0];
    const int*   ei    = (const int*)d_in[1];
    const int*   batch = (const int*)d_in[2];
    const float* W[4]   = {(const float*)d_in[3],  (const float*)d_in[7],
                           (const float*)d_in[11], (const float*)d_in[15]};
    const float* Asrc[4] = {(const float*)d_in[4],  (const float*)d_in[8],
                            (const float*)d_in[12], (const float*)d_in[16]};
    const float* Adst[4] = {(const float*)d_in[5],  (const float*)d_in[9],
                            (const float*)d_in[13], (const float*)d_in[17]};
    const float* Bb[4]   = {(const float*)d_in[6],  (const float*)d_in[10],
                            (const float*)d_in[14], (const float*)d_in[18]};
    const float* lw1 = (const float*)d_in[19]; const float* lb1 = (const float*)d_in[20];
    const float* lw2 = (const float*)d_in[21]; const float* lb2 = (const float*)d_in[22];
    const float* lw3 = (const float*)d_in[23]; const float* lb3 = (const float*)d_in[24];
    const float* lw4 = (const float*)d_in[25]; const float* lb4 = (const float*)d_in[26];
    float* out = (float*)d_out;

    float *hP, *faP, *fbP, *poolP, *l1P, *l2P, *l3P;
    cudaGetSymbolAddress((void**)&hP,    g_h);
    cudaGetSymbolAddress((void**)&faP,   g_fa);
    cudaGetSymbolAddress((void**)&fbP,   g_fb);
    cudaGetSymbolAddress((void**)&poolP, g_pool);
    cudaGetSymbolAddress((void**)&l1P,   g_l1);
    cudaGetSymbolAddress((void**)&l2P,   g_l2);
    cudaGetSymbolAddress((void**)&l3P,   g_l3);

    // CSR build (per launch; edges are an input)
    zero_cnt_kernel<<<(NN + 255) / 256, 256>>>();
    count_kernel<<<(ET + 255) / 256, 256>>>(ei);
    scan_kernel<<<1, 1024>>>();
    init_pos_kernel<<<(NN + 255) / 256, 256>>>();
    scatter_kernel<<<(ET + 255) / 256, 256>>>(ei);

    const float* fin = x;
    int K = 336;
    float* fouts[4] = {faP, fbP, faP, fbP};
    dim3 ggrid((CHN + BN - 1) / BN, (NN + BM - 1) / BM);
    for (int l = 0; l < 4; l++) {
        gemm_kernel<<<ggrid, 256>>>(fin, W[l], hP, NN, K, CHN);
        att_kernel<<<(NN + 3) / 4, 128>>>(Asrc[l], Adst[l]);
        agg_kernel<<<NN, 128>>>(Bb[l], fouts[l]);
        fin = fouts[l];
        K = CHN;
    }

    pool_kernel<<<GG, 256>>>(batch, fouts[3]);

    lin_kernel<<<(GG * 200 + 127) / 128, 128>>>(poolP, lw1, lb1, l1P, GG, 250, 200, 1);
    lin_kernel<<<(GG * 100 + 127) / 128, 128>>>(l1P,   lw2, lb2, l2P, GG, 200, 100, 1);
    lin_kernel<<<(GG * 100 + 127) / 128, 128>>>(l2P,   lw3, lb3, l3P, GG, 100, 100, 1);
    lin_kernel<<<(GG * 29  + 127) / 128, 128>>>(l3P,   lw4, lb4, out, GG, 100, 29,  0);
}

// round 5
// speedup vs baseline: 1.1360x; 1.1360x over previous
#include <cuda_runtime.h>
#include <cuda_bf16.h>
#include <mma.h>
#include <cstdint>

using namespace nvcuda;

#define NN    10000
#define EE    320000
#define ET    330000    // EE + NN self loops
#define GG    100
#define CHN   250       // HEADS*OUT
#define HOUT  125
#define SLOPE 0.2f

#define MT    128       // GEMM M tile
#define NT    256       // padded N
#define MPAD  10112     // 79 * 128
#define KP1   384       // K=336 padded
#define KP2   256       // K=250 padded
#define BK    32

// ---------------- scratch (static device globals; no allocation) -------------
__device__ float g_h[NN * CHN];
__device__ float g_fa[NN * CHN];
__device__ float g_fb[NN * CHN];
__device__ float g_esrc[NN * 2];
__device__ float g_edst[NN * 2];
__device__ int   g_cnt[NN];
__device__ int   g_off[NN + 1];
__device__ int   g_pos[NN];
__device__ int   g_csr[ET];
__device__ float g_pool[GG * CHN];
__device__ float g_l1[GG * 200];
__device__ float g_l2[GG * 100];
__device__ float g_l3[GG * 100];
__device__ __align__(256) __nv_bfloat16 g_ahi[MPAD * KP1];
__device__ __align__(256) __nv_bfloat16 g_alo[MPAD * KP1];
__device__ __align__(256) __nv_bfloat16 g_whi[NT * KP1];
__device__ __align__(256) __nv_bfloat16 g_wlo[NT * KP1];

// ---------------- helpers ------------------------------------------------------
__device__ __forceinline__ uint32_t smem_u32(const void* p) {
    uint32_t a;
    asm("{ .reg .u64 t; cvta.to.shared.u64 t, %1; cvt.u32.u64 %0, t; }" : "=r"(a) : "l"(p));
    return a;
}
__device__ __forceinline__ void cp_async16(uint32_t dst, const void* src) {
    asm volatile("cp.async.cg.shared.global [%0], [%1], 16;" :: "r"(dst), "l"(src));
}
__device__ __forceinline__ void cp_commit() {
    asm volatile("cp.async.commit_group;" ::: "memory");
}
__device__ __forceinline__ void cp_wait0() {
    asm volatile("cp.async.wait_group 0;" ::: "memory");
}
__device__ __forceinline__ void cp_wait1() {
    asm volatile("cp.async.wait_group 1;" ::: "memory");
}

// ---------------- CSR build --------------------------------------------------
__global__ void zero_cnt_kernel() {
    int i = blockIdx.x * blockDim.x + threadIdx.x;
    if (i < NN) g_cnt[i] = 0;
}
__global__ void count_kernel(const int* __restrict__ ei) {
    int i = blockIdx.x * blockDim.x + threadIdx.x;
    if (i >= ET) return;
    int dst = (i < EE) ? ei[EE + i] : (i - EE);
    atomicAdd(&g_cnt[dst], 1);
}
__global__ void scan_kernel() {
    __shared__ int sp[1024];
    int t = threadIdx.x;
    int base = t * 10;
    int loc[10];
    int sum = 0;
#pragma unroll
    for (int i = 0; i < 10; i++) {
        int idx = base + i;
        int v = (idx < NN) ? g_cnt[idx] : 0;
        loc[i] = sum; sum += v;
    }
    sp[t] = sum;
    __syncthreads();
    for (int off = 1; off < 1024; off <<= 1) {
        int v = (t >= off) ? sp[t - off] : 0;
        __syncthreads();
        sp[t] += v;
        __syncthreads();
    }
    int pre = sp[t] - sum;
#pragma unroll
    for (int i = 0; i < 10; i++) {
        int idx = base + i;
        if (idx < NN) g_off[idx] = pre + loc[i];
    }
    if (t == 1023) g_off[NN] = sp[1023];
}
__global__ void init_pos_kernel() {
    int i = blockIdx.x * blockDim.x + threadIdx.x;
    if (i < NN) g_pos[i] = g_off[i];
}
__global__ void scatter_kernel(const int* __restrict__ ei) {
    int i = blockIdx.x * blockDim.x + threadIdx.x;
    if (i >= ET) return;
    int src, dst;
    if (i < EE) { src = ei[i]; dst = ei[EE + i]; }
    else        { src = i - EE; dst = i - EE; }
    int p = atomicAdd(&g_pos[dst], 1);
    g_csr[p] = src;
}

// ---------------- fp32 -> bf16 hi/lo split ------------------------------------
__global__ void split_a_kernel(const float* __restrict__ in, int K, int Kpad) {
    int idx = blockIdx.x * blockDim.x + threadIdx.x;
    if (idx >= MPAD * Kpad) return;
    int r = idx / Kpad, k = idx - r * Kpad;
    float v = (r < NN && k < K) ? in[(size_t)r * K + k] : 0.f;
    __nv_bfloat16 h = __float2bfloat16(v);
    __nv_bfloat16 l = __float2bfloat16(v - __bfloat162float(h));
    g_ahi[idx] = h; g_alo[idx] = l;
}
__global__ void split_w_kernel(const float* __restrict__ W, int K, int Kpad) {
    int idx = blockIdx.x * blockDim.x + threadIdx.x;
    if (idx >= NT * Kpad) return;
    int n = idx / Kpad, k = idx - n * Kpad;
    float v = (n < CHN && k < K) ? W[(size_t)k * CHN + n] : 0.f;
    __nv_bfloat16 h = __float2bfloat16(v);
    __nv_bfloat16 l = __float2bfloat16(v - __bfloat162float(h));
    g_whi[idx] = h; g_wlo[idx] = l;
}

// ---------------- WMMA bf16 GEMM (hi/lo split via K-concatenation) ------------
// C = Ahi*Bhi + Ahi*Blo + Alo*Bhi  folded as K' = 3*Kpad segments.
// Block tile 128x128, 8 warps (4m x 2n), warp tile 32x64, BK=32, cp.async 2-stage.
#define ALD  40    // A smem row lead (bf16 elems)
#define BLD  40
#define CLD  136   // C smem row lead (f32 elems)
#define A_ST (128 * ALD)             // elems per A stage
#define B_ST (128 * BLD)

__global__ __launch_bounds__(256) void gemm_wmma_kernel(
    const __nv_bfloat16* __restrict__ Ahi, const __nv_bfloat16* __restrict__ Alo,
    const __nv_bfloat16* __restrict__ Bhi, const __nv_bfloat16* __restrict__ Blo,
    int Kpad, float* __restrict__ hout)
{
    extern __shared__ char smem[];
    __nv_bfloat16* As = (__nv_bfloat16*)smem;                  // [2][128][ALD]
    __nv_bfloat16* Bs = (__nv_bfloat16*)smem + 2 * A_ST;       // [2][128][BLD]
    float* Cs = (float*)smem;                                   // [128][CLD] (reuse)

    int tid = threadIdx.x;
    int wid = tid >> 5;
    int wm = wid >> 1;          // 0..3  warp row
    int wn = wid & 1;           // 0..1  warp col
    int m0 = blockIdx.x * MT;
    int n0 = blockIdx.y * 128;

    uint32_t asmem = smem_u32(As);
    uint32_t bsmem = smem_u32(Bs);

    int row = tid >> 2;          // 0..63 (x2 iters covers 128)
    int grp = tid & 3;           // 16B chunk within 32-elem row

    int niter = (3 * Kpad) >> 5;  // K' / 32

    // -------- load one stage via cp.async --------
    auto load_stage = [&](int st, int kb) {
        int kp = kb << 5;                   // global k'
        int seg = kp / Kpad;
        int kk = kp - seg * Kpad;
        const __nv_bfloat16* aseg = (seg < 2) ? Ahi : Alo;
        const __nv_bfloat16* bseg = (seg == 1) ? Blo : Bhi;
#pragma unroll
        for (int i = 0; i < 2; i++) {
            int r = row + i * 64;
            uint32_t d = asmem + (st * A_ST + r * ALD + grp * 8) * 2;
            cp_async16(d, aseg + (size_t)(m0 + r) * Kpad + kk + grp * 8);
        }
#pragma unroll
        for (int i = 0; i < 2; i++) {
            int r = row + i * 64;
            uint32_t d = bsmem + (st * B_ST + r * BLD + grp * 8) * 2;
            cp_async16(d, bseg + (size_t)(n0 + r) * Kpad + kk + grp * 8);
        }
        cp_commit();
    };

    wmma::fragment<wmma::accumulator, 16, 16, 16, float> c[2][4];
#pragma unroll
    for (int i = 0; i < 2; i++)
#pragma unroll
        for (int j = 0; j < 4; j++) wmma::fill_fragment(c[i][j], 0.f);

    load_stage(0, 0);
    for (int kb = 0; kb < niter; kb++) {
        int st = kb & 1;
        if (kb + 1 < niter) { load_stage(st ^ 1, kb + 1); cp_wait1(); }
        else                { cp_wait0(); }
        __syncthreads();

        const __nv_bfloat16* at = As + st * A_ST + wm * 32 * ALD;
        const __nv_bfloat16* bt = Bs + st * B_ST + wn * 64 * BLD;
#pragma unroll
        for (int ks = 0; ks < 2; ks++) {
            wmma::fragment<wmma::matrix_a, 16, 16, 16, __nv_bfloat16, wmma::row_major> a0, a1;
            wmma::load_matrix_sync(a0, at + ks * 16, ALD);
            wmma::load_matrix_sync(a1, at + 16 * ALD + ks * 16, ALD);
#pragma unroll
            for (int j = 0; j < 4; j++) {
                wmma::fragment<wmma::matrix_b, 16, 16, 16, __nv_bfloat16, wmma::col_major> b;
                wmma::load_matrix_sync(b, bt + j * 16 * BLD + ks * 16, BLD);
                wmma::mma_sync(c[0][j], a0, b, c[0][j]);
                wmma::mma_sync(c[1][j], a1, b, c[1][j]);
            }
        }
        __syncthreads();
    }

    // -------- epilogue: c frags -> smem -> coalesced global store --------
#pragma unroll
    for (int i = 0; i < 2; i++)
#pragma unroll
        for (int j = 0; j < 4; j++)
            wmma::store_matrix_sync(Cs + (wm * 32 + i * 16) * CLD + wn * 64 + j * 16,
                                    c[i][j], CLD, wmma::mem_row_major);
    __syncthreads();

#pragma unroll
    for (int it = 0; it < 64; it++) {
        int idx = it * 256 + tid;
        int r = idx >> 7, cc = idx & 127;
        int grow = m0 + r, gcol = n0 + cc;
        if (grow < NN && gcol < CHN)
            hout[(size_t)grow * CHN + gcol] = Cs[r * CLD + cc];
    }
}

// ---------------- attention dot products per node ----------------------------
__global__ void att_kernel(const float* __restrict__ asrc,
                           const float* __restrict__ adst)
{
    int warp = threadIdx.x >> 5;
    int lane = threadIdx.x & 31;
    int n = blockIdx.x * 4 + warp;
    if (n >= NN) return;
    float s0s = 0.f, s1s = 0.f, s0d = 0.f, s1d = 0.f;
    const float* hr = g_h + (size_t)n * CHN;
    for (int c = lane; c < CHN; c += 32) {
        float v = hr[c];
        float as = asrc[c], ad = adst[c];
        if (c < HOUT) { s0s += v * as; s0d += v * ad; }
        else          { s1s += v * as; s1d += v * ad; }
    }
#pragma unroll
    for (int o = 16; o; o >>= 1) {
        s0s += __shfl_xor_sync(0xffffffffu, s0s, o);
        s1s += __shfl_xor_sync(0xffffffffu, s1s, o);
        s0d += __shfl_xor_sync(0xffffffffu, s0d, o);
        s1d += __shfl_xor_sync(0xffffffffu, s1d, o);
    }
    if (lane == 0) {
        g_esrc[2 * n + 0] = s0s;
        g_esrc[2 * n + 1] = s1s;
        g_edst[2 * n + 0] = s0d;
        g_edst[2 * n + 1] = s1d;
    }
}

__device__ __forceinline__ float leaky(float x) { return x > 0.f ? x : SLOPE * x; }

// ---------------- aggregation: one block per destination node ----------------
__global__ __launch_bounds__(128) void agg_kernel(const float* __restrict__ bias,
                                                  float* __restrict__ out)
{
    int i = blockIdx.x;
    int tid = threadIdx.x;
    int lane = tid & 31, warp = tid >> 5;

    __shared__ float w0[4], w1[4];
    __shared__ int   s_src[128];
    __shared__ float s_a0[128], s_a1[128];

    int s = g_off[i], e = g_off[i + 1];
    float ed0 = g_edst[2 * i], ed1 = g_edst[2 * i + 1];

    float m0 = -1e30f, m1 = -1e30f;
    for (int j = s + tid; j < e; j += 128) {
        int src = g_csr[j];
        float a0 = leaky(g_esrc[2 * src] + ed0);
        float a1 = leaky(g_esrc[2 * src + 1] + ed1);
        m0 = fmaxf(m0, a0); m1 = fmaxf(m1, a1);
    }
#pragma unroll
    for (int o = 16; o; o >>= 1) {
        m0 = fmaxf(m0, __shfl_xor_sync(0xffffffffu, m0, o));
        m1 = fmaxf(m1, __shfl_xor_sync(0xffffffffu, m1, o));
    }
    if (lane == 0) { w0[warp] = m0; w1[warp] = m1; }
    __syncthreads();
    m0 = fmaxf(fmaxf(w0[0], w0[1]), fmaxf(w0[2], w0[3]));
    m1 = fmaxf(fmaxf(w1[0], w1[1]), fmaxf(w1[2], w1[3]));
    __syncthreads();

    float d0 = 0.f, d1 = 0.f;
    for (int j = s + tid; j < e; j += 128) {
        int src = g_csr[j];
        float a0 = leaky(g_esrc[2 * src] + ed0);
        float a1 = leaky(g_esrc[2 * src + 1] + ed1);
        d0 += __expf(a0 - m0);
        d1 += __expf(a1 - m1);
    }
#pragma unroll
    for (int o = 16; o; o >>= 1) {
        d0 += __shfl_xor_sync(0xffffffffu, d0, o);
        d1 += __shfl_xor_sync(0xffffffffu, d1, o);
    }
    if (lane == 0) { w0[warp] = d0; w1[warp] = d1; }
    __syncthreads();
    d0 = w0[0] + w0[1] + w0[2] + w0[3] + 1e-16f;
    d1 = w1[0] + w1[1] + w1[2] + w1[3] + 1e-16f;
    float r0 = 1.0f / d0, r1 = 1.0f / d1;

    float acc0 = 0.f, acc1 = 0.f;
    int c0 = 2 * tid;
    bool act = (tid < HOUT);
    bool head0a = (c0 < HOUT);
    bool head0b = (c0 + 1 < HOUT);

    for (int base = s; base < e; base += 128) {
        int j = base + tid;
        if (j < e) {
            int src = g_csr[j];
            float a0 = leaky(g_esrc[2 * src] + ed0);
            float a1 = leaky(g_esrc[2 * src + 1] + ed1);
            s_src[tid] = src;
            s_a0[tid] = __expf(a0 - m0) * r0;
            s_a1[tid] = __expf(a1 - m1) * r1;
        }
        __syncthreads();
        int cnt = min(128, e - base);
        if (act) {
#pragma unroll 4
            for (int k = 0; k < cnt; k++) {
                int src = s_src[k];
                float2 hv = *(const float2*)(g_h + (size_t)src * CHN + c0);
                float aa = head0a ? s_a0[k] : s_a1[k];
                float ab = head0b ? s_a0[k] : s_a1[k];
                acc0 += aa * hv.x;
                acc1 += ab * hv.y;
            }
        }
        __syncthreads();
    }
    if (act) {
        float v0 = acc0 + bias[c0];
        float v1 = acc1 + bias[c0 + 1];
        out[(size_t)i * CHN + c0]     = v0 > 0.f ? v0 : 0.f;
        out[(size_t)i * CHN + c0 + 1] = v1 > 0.f ? v1 : 0.f;
    }
}

// ---------------- global mean pool -------------------------------------------
__global__ void pool_kernel(const int* __restrict__ batch,
                            const float* __restrict__ feat)
{
    int g = blockIdx.x;
    __shared__ int ss, se;
    if (threadIdx.x == 0) {
        int lo = 0, hi = NN;
        while (lo < hi) { int mid = (lo + hi) >> 1; if (batch[mid] < g) lo = mid + 1; else hi = mid; }
        ss = lo;
        lo = 0; hi = NN;
        while (lo < hi) { int mid = (lo + hi) >> 1; if (batch[mid] < g + 1) lo = mid + 1; else hi = mid; }
        se = lo;
    }
    __syncthreads();
    int c = threadIdx.x;
    if (c < CHN) {
        float sum = 0.f;
        for (int i = ss; i < se; i++) sum += feat[(size_t)i * CHN + c];
        float cntf = (float)(se - ss);
        g_pool[g * CHN + c] = sum / fmaxf(cntf, 1.0f);
    }
}

// ---------------- tiny linear layers -----------------------------------------
__global__ void lin_kernel(const float* __restrict__ in, const float* __restrict__ w,
                           const float* __restrict__ b, float* __restrict__ out,
                           int Gr, int K, int Dout, int relu)
{
    int idx = blockIdx.x * blockDim.x + threadIdx.x;
    if (idx >= Gr * Dout) return;
    int g = idx / Dout, j = idx % Dout;
    float s = b[j];
    for (int k = 0; k < K; k++) s += in[g * K + k] * w[k * Dout + j];
    if (relu) s = fmaxf(s, 0.f);
    out[idx] = s;
}

// ---------------- driver ------------------------------------------------------
#define GEMM_SMEM (128 * CLD * 4)   // 69632 (C reuse >= tile region 40960)

extern "C" void kernel_launch(void* const* d_in, const int* in_sizes, int n_in,
                              void* d_out, int out_size)
{
    const float* x     = (const float*)d_in[0];
    const int*   ei    = (const int*)d_in[1];
    const int*   batch = (const int*)d_in[2];
    const float* W[4]    = {(const float*)d_in[3],  (const float*)d_in[7],
                            (const float*)d_in[11], (const float*)d_in[15]};
    const float* Asrc[4] = {(const float*)d_in[4],  (const float*)d_in[8],
                            (const float*)d_in[12], (const float*)d_in[16]};
    const float* Adst[4] = {(const float*)d_in[5],  (const float*)d_in[9],
                            (const float*)d_in[13], (const float*)d_in[17]};
    const float* Bb[4]   = {(const float*)d_in[6],  (const float*)d_in[10],
                            (const float*)d_in[14], (const float*)d_in[18]};
    const float* lw1 = (const float*)d_in[19]; const float* lb1 = (const float*)d_in[20];
    const float* lw2 = (const float*)d_in[21]; const float* lb2 = (const float*)d_in[22];
    const float* lw3 = (const float*)d_in[23]; const float* lb3 = (const float*)d_in[24];
    const float* lw4 = (const float*)d_in[25]; const float* lb4 = (const float*)d_in[26];
    float* out = (float*)d_out;

    float *hP, *faP, *fbP, *poolP, *l1P, *l2P, *l3P;
    __nv_bfloat16 *ahiP, *aloP, *whiP, *wloP;
    cudaGetSymbolAddress((void**)&hP,    g_h);
    cudaGetSymbolAddress((void**)&faP,   g_fa);
    cudaGetSymbolAddress((void**)&fbP,   g_fb);
    cudaGetSymbolAddress((void**)&poolP, g_pool);
    cudaGetSymbolAddress((void**)&l1P,   g_l1);
    cudaGetSymbolAddress((void**)&l2P,   g_l2);
    cudaGetSymbolAddress((void**)&l3P,   g_l3);
    cudaGetSymbolAddress((void**)&ahiP,  g_ahi);
    cudaGetSymbolAddress((void**)&aloP,  g_alo);
    cudaGetSymbolAddress((void**)&whiP,  g_whi);
    cudaGetSymbolAddress((void**)&wloP,  g_wlo);

    cudaFuncSetAttribute(gemm_wmma_kernel,
                         cudaFuncAttributeMaxDynamicSharedMemorySize, GEMM_SMEM);

    // CSR build
    zero_cnt_kernel<<<(NN + 255) / 256, 256>>>();
    count_kernel<<<(ET + 255) / 256, 256>>>(ei);
    scan_kernel<<<1, 1024>>>();
    init_pos_kernel<<<(NN + 255) / 256, 256>>>();
    scatter_kernel<<<(ET + 255) / 256, 256>>>(ei);

    const float* fin = x;
    float* fouts[4] = {faP, fbP, faP, fbP};
    int Ks[4]    = {336, 250, 250, 250};
    int Kpads[4] = {KP1, KP2, KP2, KP2};

    dim3 ggrid(MPAD / MT, 2);
    for (int l = 0; l < 4; l++) {
        int K = Ks[l], Kpad = Kpads[l];
        split_a_kernel<<<(MPAD * Kpad + 255) / 256, 256>>>(fin, K, Kpad);
        split_w_kernel<<<(NT * Kpad + 255) / 256, 256>>>(W[l], K, Kpad);
        gemm_wmma_kernel<<<ggrid, 256, GEMM_SMEM>>>(ahiP, aloP, whiP, wloP, Kpad, hP);
        att_kernel<<<(NN + 3) / 4, 128>>>(Asrc[l], Adst[l]);
        agg_kernel<<<NN, 128>>>(Bb[l], fouts[l]);
        fin = fouts[l];
    }

    pool_kernel<<<GG, 256>>>(batch, fouts[3]);

    lin_kernel<<<(GG * 200 + 127) / 128, 128>>>(poolP, lw1, lb1, l1P, GG, 250, 200, 1);
    lin_kernel<<<(GG * 100 + 127) / 128, 128>>>(l1P,   lw2, lb2, l2P, GG, 200, 100, 1);
    lin_kernel<<<(GG * 100 + 127) / 128, 128>>>(l2P,   lw3, lb3, l3P, GG, 100, 100, 1);
    lin_kernel<<<(GG * 29  + 127) / 128, 128>>>(l3P,   lw4, lb4, out, GG, 100, 29,  0);
}